// round 13
// baseline (speedup 1.0000x reference)
#include <cuda_runtime.h>
#include <math.h>
#include <stdint.h>

// Problem constants
#define Bc 2
#define Lc 2048
#define Dc 1024
#define Hc 16
#define Dhc 64
#define Mg (Bc*Lc)          // 4096

// Scratch
__device__ float g_q[(size_t)Bc*Hc*Lc*Dhc];
__device__ float g_k[(size_t)Bc*Hc*Lc*Dhc];
__device__ float g_v[(size_t)Bc*Hc*Lc*Dhc];
__device__ float g_o[(size_t)Bc*Lc*Dc];
__device__ float g_xc[(size_t)Mg*Dc];        // x, tf32-rounded, [m][k]
__device__ float g_wc[(size_t)4*Dc*Dc];      // W^T {q,k,v,o}: [n][k], tf32 (Wq pre-scaled)

// ---------------------------------------------------------------------------
// Helpers
// ---------------------------------------------------------------------------
__device__ __forceinline__ uint32_t f2tf32(float f) {
    uint32_t u;
    asm("cvt.rna.tf32.f32 %0, %1;" : "=r"(u) : "f"(f));
    return u;
}

__device__ __forceinline__ float ex2(float x) {
    float r;
    asm("ex2.approx.f32 %0, %1;" : "=f"(r) : "f"(x));
    return r;
}

__device__ __forceinline__ uint32_t smem_u32(const void* p) {
    uint32_t a;
    asm("{ .reg .u64 t; cvta.to.shared.u64 t, %1; cvt.u32.u64 %0, t; }"
        : "=r"(a) : "l"(p));
    return a;
}

__device__ __forceinline__ void cpa16(uint32_t s, const void* g) {
    asm volatile("cp.async.cg.shared.global [%0], [%1], 16;" :: "r"(s), "l"(g));
}
#define CP_COMMIT() asm volatile("cp.async.commit_group;" ::: "memory")
#define CP_WAIT(n)  asm volatile("cp.async.wait_group %0;" :: "n"(n) : "memory")

__device__ __forceinline__ void mma_tf32(float* c, const uint32_t* a, const uint32_t* b) {
    asm volatile(
        "mma.sync.aligned.m16n8k8.row.col.f32.tf32.tf32.f32 "
        "{%0,%1,%2,%3}, {%4,%5,%6,%7}, {%8,%9}, {%0,%1,%2,%3};"
        : "+f"(c[0]), "+f"(c[1]), "+f"(c[2]), "+f"(c[3])
        : "r"(a[0]), "r"(a[1]), "r"(a[2]), "r"(a[3]), "r"(b[0]), "r"(b[1]));
}

// x4 ldmatrix: 4 8x(4x32b) tiles; thread gets [row=lane/4][col32=lane%4]
#define LDSM4(r, a) \
    asm volatile("ldmatrix.sync.aligned.m8n8.x4.shared.b16 {%0,%1,%2,%3}, [%4];" \
        : "=r"((r)[0]), "=r"((r)[1]), "=r"((r)[2]), "=r"((r)[3]) : "r"(a))

// ---------------------------------------------------------------------------
// Prep A: tf32-round x.
// ---------------------------------------------------------------------------
__global__ __launch_bounds__(256)
void prep_x_kernel(const float* __restrict__ x)
{
    const size_t n = (size_t)Mg * Dc;
    const size_t stride = (size_t)gridDim.x * 256 * 4;
    for (size_t i = ((size_t)blockIdx.x * 256 + threadIdx.x) * 4; i < n; i += stride) {
        float4 v = *(const float4*)(x + i);
        uint4 u;
        u.x = f2tf32(v.x); u.y = f2tf32(v.y);
        u.z = f2tf32(v.z); u.w = f2tf32(v.w);
        *(uint4*)(g_xc + i) = u;
    }
}

// ---------------------------------------------------------------------------
// Prep B: transpose weights to [n][k] + tf32 round. Wq gets (1/8)*log2(e).
// ---------------------------------------------------------------------------
__global__ __launch_bounds__(256)
void prep_w_kernel(const float* __restrict__ Wq, const float* __restrict__ Wk,
                   const float* __restrict__ Wv, const float* __restrict__ Wo)
{
    __shared__ float tile[32][33];
    const int z = blockIdx.z;
    const float* src = (z == 0) ? Wq : (z == 1) ? Wk : (z == 2) ? Wv : Wo;
    float* dst = g_wc + (size_t)z * 1048576;
    const float scale = (z == 0) ? 0.18033688011112042f : 1.0f;
    const int k0 = blockIdx.x * 32, n0 = blockIdx.y * 32;
    const int tx = threadIdx.x & 31, ty = threadIdx.x >> 5;
#pragma unroll
    for (int i = ty; i < 32; i += 8)
        tile[i][tx] = src[(size_t)(k0 + i) * 1024 + n0 + tx];
    __syncthreads();
#pragma unroll
    for (int i = ty; i < 32; i += 8)
        dst[(size_t)(n0 + i) * 1024 + k0 + tx] =
            __uint_as_float(f2tf32(tile[tx][i] * scale));
}

// ---------------------------------------------------------------------------
// cp.async 3-stage TF32 GEMM, ldmatrix fragment loads.
// C[M,N] = A[M,K] * B^T[N,K]^T, K=1024. Block 256x128, 8 warps (4x2),
// warp tile 64x64, k-chunk 32. Per k-step: 8 LDSM.x4 feed 32 MMAs.
// As [256][36], Bs [128][36] (both k-contiguous rows; stride%32=4 -> LDSM
// phases conflict-free).
// mode 0: A=g_xc, B=g_wc[z], scatter tf32-rounded into g_q/g_k/g_v
// mode 1: A=g_o,  B=g_wc[3], plain fp32 row-major out
// ---------------------------------------------------------------------------
#define SA 36
#define A_ST_FL (256*SA)                 // 9216 floats
#define B_ST_FL (128*SA)                 // 4608 floats
#define STG_FL  (A_ST_FL + B_ST_FL)      // 13824
#define STG_BYTES (STG_FL*4)             // 55296
#define GEMM_SMEM (3*STG_BYTES)          // 165888 B

__global__ __launch_bounds__(256, 1)
void mma_gemm(float* __restrict__ Dst, int mode)
{
    extern __shared__ float sm[];
    const uint32_t sb = smem_u32(sm);

    const int tid = threadIdx.x;
    const int lane = tid & 31, wid = tid >> 5;
    const int g = lane >> 2, t = lane & 3;
    const int wr = wid >> 1, wc = wid & 1;

    const int n0 = blockIdx.x * 128;
    const int m0 = blockIdx.y * 256;
    const int z  = blockIdx.z;

    const float* A  = (mode == 0) ? g_xc : g_o;
    const float* Bt = g_wc + (size_t)((mode == 0) ? z : 3) * 1048576;

    // cp.async source/dst mapping: row = it*32 + (tid>>3), seg = tid&7
    const float* Agp = A  + (size_t)(m0 + (tid >> 3)) * 1024 + (tid & 7) * 4;
    const float* Bgp = Bt + (size_t)(n0 + (tid >> 3)) * 1024 + (tid & 7) * 4;
    const uint32_t aoff = (uint32_t)(tid >> 3) * (SA * 4) + (tid & 7) * 16;
    const uint32_t boff = (uint32_t)(A_ST_FL * 4) + aoff;

#define G_ISSUE(ch) do { \
    const uint32_t st_ = sb + (uint32_t)((ch) % 3) * STG_BYTES; \
    const float* ag_ = Agp + (ch) * 32; \
    const float* bg_ = Bgp + (ch) * 32; \
    _Pragma("unroll") \
    for (int i_ = 0; i_ < 8; i_++) \
        cpa16(st_ + aoff + i_ * 32 * (SA * 4), ag_ + (size_t)i_ * 32 * 1024); \
    _Pragma("unroll") \
    for (int i_ = 0; i_ < 4; i_++) \
        cpa16(st_ + boff + i_ * 32 * (SA * 4), bg_ + (size_t)i_ * 32 * 1024); \
} while (0)

    float c[4][8][4];
#pragma unroll
    for (int mi = 0; mi < 4; mi++)
#pragma unroll
        for (int ni = 0; ni < 8; ni++)
#pragma unroll
            for (int q = 0; q < 4; q++) c[mi][ni][q] = 0.f;

    G_ISSUE(0); CP_COMMIT();
    G_ISSUE(1); CP_COMMIT();

    const int mbase = 64 * wr, nbase = 64 * wc;

    // ldmatrix per-thread row addressing (byte offsets from stage base):
    // A: matrices {rows 0-7 k0-3, rows 8-15 k0-3, rows 0-7 k4-7, rows 8-15 k4-7}
    const uint32_t a_lm = (uint32_t)((mbase + (lane & 15)) * SA + (lane >> 4) * 4) * 4;
    // B: matrices {n 0-7 k0-3, n 0-7 k4-7, n 8-15 k0-3, n 8-15 k4-7}
    const uint32_t b_lm = (uint32_t)(A_ST_FL * 4)
        + (uint32_t)((nbase + 8 * (lane >> 4) + (lane & 7)) * SA + ((lane >> 3) & 1) * 4) * 4;

    for (int ch = 0; ch < 32; ch++) {
        CP_WAIT(1);
        __syncthreads();                    // stage ch visible; compute ch-1 done
        if (ch + 2 < 32) G_ISSUE(ch + 2);
        CP_COMMIT();

        const uint32_t st = sb + (uint32_t)(ch % 3) * STG_BYTES;
        const uint32_t aB = st + a_lm;
        const uint32_t bB = st + b_lm;
#pragma unroll
        for (int ks = 0; ks < 4; ks++) {
            const int kk = ks * 8;
            uint32_t af[4][4], bf[4][4];
#pragma unroll
            for (int mi = 0; mi < 4; mi++)
                LDSM4(af[mi], aB + (uint32_t)(mi * 16 * SA + kk) * 4);
#pragma unroll
            for (int p = 0; p < 4; p++)
                LDSM4(bf[p], bB + (uint32_t)(p * 16 * SA + kk) * 4);
#pragma unroll
            for (int mi = 0; mi < 4; mi++)
#pragma unroll
                for (int ni = 0; ni < 8; ni++)
                    mma_tf32(c[mi][ni], af[mi], &bf[ni >> 1][2 * (ni & 1)]);
        }
    }

    // Epilogue. mode 0: tf32-round (consumers feed mma directly).
    float* gz = (mode == 0) ? ((z == 0) ? g_q : (z == 1) ? g_k : g_v) : Dst;
#pragma unroll
    for (int mi = 0; mi < 4; mi++) {
#pragma unroll
        for (int half = 0; half < 2; half++) {
            const int mglob = m0 + mbase + 16*mi + g + 8*half;
#pragma unroll
            for (int ni = 0; ni < 8; ni++) {
                const int nglob = n0 + nbase + 8*ni + 2*t;
                float2 v;
                v.x = c[mi][ni][2*half + 0];
                v.y = c[mi][ni][2*half + 1];
                if (mode == 0) {
                    v.x = __uint_as_float(f2tf32(v.x));
                    v.y = __uint_as_float(f2tf32(v.y));
                    const int b = mglob >> 11, l = mglob & 2047;
                    const int h = nglob >> 6, e = nglob & 63;
                    *(float2*)&gz[(((size_t)(b*Hc + h) * Lc + l) << 6) + e] = v;
                } else {
                    *(float2*)&gz[(size_t)mglob * 1024 + nglob] = v;
                }
            }
        }
    }
}

// ---------------------------------------------------------------------------
// TF32 tensor-core causal flash attention. ldmatrix for Q/K/P fragments
// (K is naturally [n][k]); V stays scalar LDS. K/V split commit groups.
// Block: 128 q-rows (8 warps x 16), K-tile 64.
// ---------------------------------------------------------------------------
#define SQf 68
#define SKf 68
#define SVf 72
#define SPf 68
#define QS_OFF 0
#define KS_OFF (128*SQf)                 // 8704
#define VS_OFF (KS_OFF + 64*SKf)         // 13056
#define PS_OFF (VS_OFF + 64*SVf)         // 17664
#define FL_FLOATS (PS_OFF + 128*SPf)     // 26368
#define FL_SMEM (FL_FLOATS * 4)          // 105472 B

__global__ __launch_bounds__(256, 2)
void flash_kernel()
{
    extern __shared__ float sm[];
    const uint32_t sb = smem_u32(sm);
    float* Ps = sm + PS_OFF;
    float* Vs = sm + VS_OFF;

    const int qt = gridDim.x - 1 - blockIdx.x;   // heavy tiles first
    const int bh = blockIdx.y;
    const int tid = threadIdx.x;
    const int lane = tid & 31, wid = tid >> 5;
    const int g = lane >> 2, t = lane & 3;
    const int wq0 = wid * 16;

    const float* qb = g_q + (size_t)bh * Lc * Dhc;
    const float* kb = g_k + (size_t)bh * Lc * Dhc;
    const float* vb = g_v + (size_t)bh * Lc * Dhc;

    // ldmatrix bases (byte offsets)
    const uint32_t q_lm = sb + (uint32_t)((wq0 + (lane & 15)) * SQf + (lane >> 4) * 4) * 4;
    const uint32_t k_lm = sb + (uint32_t)(KS_OFF
        + (8 * (lane >> 4) + (lane & 7)) * SKf + ((lane >> 3) & 1) * 4) * 4;
    const uint32_t p_lm = sb + (uint32_t)(PS_OFF
        + (wq0 + (lane & 15)) * SPf + (lane >> 4) * 4) * 4;

    // Q tile (128 x 64) via cp.async (already scaled + tf32)
#pragma unroll
    for (int it = 0; it < 8; it++) {
        const int idx = it * 256 + tid;
        const int r = idx >> 4, c4 = (idx & 15) * 4;
        cpa16(sb + (uint32_t)(r * SQf + c4) * 4,
              qb + (size_t)(qt * 128 + r) * 64 + c4);
    }
    CP_COMMIT();

    float m2[2] = {-1e30f, -1e30f};
    float lsum[2] = {0.f, 0.f};
    float o[8][4];
#pragma unroll
    for (int ni = 0; ni < 8; ni++)
#pragma unroll
        for (int q = 0; q < 4; q++) o[ni][q] = 0.f;

    const int kend = 2 * qt + 1;
    for (int kt = 0; kt <= kend; kt++) {
        __syncthreads();   // prior iter's K/V reads complete
        // K group
#pragma unroll
        for (int it = 0; it < 4; it++) {
            const int idx = it * 256 + tid;
            const int r = idx >> 4, c4 = (idx & 15) * 4;
            cpa16(sb + (uint32_t)(KS_OFF + r * SKf + c4) * 4,
                  kb + (size_t)(kt * 64 + r) * 64 + c4);
        }
        CP_COMMIT();
        // V group (completes while we compute S)
#pragma unroll
        for (int it = 0; it < 4; it++) {
            const int idx = it * 256 + tid;
            const int r = idx >> 4, c4 = (idx & 15) * 4;
            cpa16(sb + (uint32_t)(VS_OFF + r * SVf + c4) * 4,
                  vb + (size_t)(kt * 64 + r) * 64 + c4);
        }
        CP_COMMIT();

        CP_WAIT(1);        // K ready (V may still be in flight)
        __syncthreads();

        // S = Q K^T  (warp: 16 x 64, k=64)
        float s[8][4];
#pragma unroll
        for (int ni = 0; ni < 8; ni++)
#pragma unroll
            for (int q = 0; q < 4; q++) s[ni][q] = 0.f;

#pragma unroll
        for (int ks = 0; ks < 8; ks++) {
            const int kk = ks * 8;
            uint32_t a[4], bf[4][4];
            LDSM4(a, q_lm + kk * 4);
#pragma unroll
            for (int p = 0; p < 4; p++)
                LDSM4(bf[p], k_lm + (uint32_t)(p * 16 * SKf + kk) * 4);
#pragma unroll
            for (int ni = 0; ni < 8; ni++)
                mma_tf32(s[ni], a, &bf[ni >> 1][2 * (ni & 1)]);
        }

        // Causal mask (near-diagonal tiles only)
        if (kt >= 2 * qt) {
            const int q0r = qt * 128 + wq0 + g;
#pragma unroll
            for (int ni = 0; ni < 8; ni++) {
                const int key0 = kt * 64 + ni * 8 + 2 * t;
                if (key0     > q0r)     s[ni][0] = -1e30f;
                if (key0 + 1 > q0r)     s[ni][1] = -1e30f;
                if (key0     > q0r + 8) s[ni][2] = -1e30f;
                if (key0 + 1 > q0r + 8) s[ni][3] = -1e30f;
            }
        }

        // Online softmax (rows g, g+8). Ps rows warp-private -> syncwarp.
        __syncwarp();
#pragma unroll
        for (int rr = 0; rr < 2; rr++) {
            float mx = -1e30f;
#pragma unroll
            for (int ni = 0; ni < 8; ni++)
                mx = fmaxf(mx, fmaxf(s[ni][2*rr], s[ni][2*rr + 1]));
            mx = fmaxf(mx, __shfl_xor_sync(0xffffffffu, mx, 1));
            mx = fmaxf(mx, __shfl_xor_sync(0xffffffffu, mx, 2));
            const float mnew = fmaxf(m2[rr], mx);
            const float corr = ex2(m2[rr] - mnew);
            float rs = 0.f;
#pragma unroll
            for (int ni = 0; ni < 8; ni++) {
                const float p0 = ex2(s[ni][2*rr]     - mnew);
                const float p1 = ex2(s[ni][2*rr + 1] - mnew);
                rs += p0 + p1;
                uint2 pw;
                pw.x = f2tf32(p0); pw.y = f2tf32(p1);
                *(uint2*)(Ps + (wq0 + g + 8*rr) * SPf + ni * 8 + 2 * t) = pw;
            }
            rs += __shfl_xor_sync(0xffffffffu, rs, 1);
            rs += __shfl_xor_sync(0xffffffffu, rs, 2);
            lsum[rr] = lsum[rr] * corr + rs;
            m2[rr] = mnew;
#pragma unroll
            for (int ni = 0; ni < 8; ni++) {
                o[ni][2*rr]     *= corr;
                o[ni][2*rr + 1] *= corr;
            }
        }
        __syncwarp();

        CP_WAIT(0);        // V ready
        __syncthreads();

        // O += P V  (P via ldmatrix, V scalar)
#pragma unroll
        for (int ks = 0; ks < 8; ks++) {
            const int k0 = ks * 8;
            uint32_t a[4];
            LDSM4(a, p_lm + k0 * 4);
#pragma unroll
            for (int ni = 0; ni < 8; ni++) {
                uint32_t b[2];
                b[0] = __float_as_uint(Vs[(k0 + t) * SVf + ni * 8 + g]);
                b[1] = __float_as_uint(Vs[(k0 + t + 4) * SVf + ni * 8 + g]);
                mma_tf32(o[ni], a, b);
            }
        }
    }

    // Epilogue: normalize, tf32-round (feeds out-proj mma), write g_o
    const float inv0 = 1.0f / lsum[0];
    const float inv1 = 1.0f / lsum[1];
    const int b = bh >> 4, h = bh & 15;
    const int q0 = qt * 128 + wq0 + g;
    const size_t base0 = ((size_t)(b * Lc + q0)) * Dc + h * Dhc;
    const size_t base1 = base0 + (size_t)8 * Dc;
#pragma unroll
    for (int ni = 0; ni < 8; ni++) {
        float2 v0, v1;
        v0.x = __uint_as_float(f2tf32(o[ni][0] * inv0));
        v0.y = __uint_as_float(f2tf32(o[ni][1] * inv0));
        v1.x = __uint_as_float(f2tf32(o[ni][2] * inv1));
        v1.y = __uint_as_float(f2tf32(o[ni][3] * inv1));
        *(float2*)&g_o[base0 + ni * 8 + 2 * t] = v0;
        *(float2*)&g_o[base1 + ni * 8 + 2 * t] = v1;
    }
}

// ---------------------------------------------------------------------------
extern "C" void kernel_launch(void* const* d_in, const int* in_sizes, int n_in,
                              void* d_out, int out_size)
{
    const float* x    = (const float*)d_in[0];
    const float* Wq   = (const float*)d_in[1];
    const float* Wk   = (const float*)d_in[2];
    const float* Wv   = (const float*)d_in[3];
    const float* Wout = (const float*)d_in[4];
    float* out = (float*)d_out;

    cudaFuncSetAttribute(mma_gemm,
                         cudaFuncAttributeMaxDynamicSharedMemorySize, GEMM_SMEM);
    cudaFuncSetAttribute(flash_kernel,
                         cudaFuncAttributeMaxDynamicSharedMemorySize, FL_SMEM);

    // 0) one-time prep: round x; transpose+round weights (Wq pre-scaled)
    prep_x_kernel<<<512, 256>>>(x);
    prep_w_kernel<<<dim3(32, 32, 4), 256>>>(Wq, Wk, Wv, Wout);

    // 1) QKV: scattered into [b][h][l][e], tf32-rounded
    mma_gemm<<<dim3(8, 16, 3), 256, GEMM_SMEM>>>(nullptr, 0);

    // 2) Flash attention (tf32 tensor cores, ldmatrix)
    flash_kernel<<<dim3(Lc / 128, Bc * Hc), 256, FL_SMEM>>>();

    // 3) Output projection
    mma_gemm<<<dim3(8, 16, 1), 256, GEMM_SMEM>>>(out, 1);
}

// round 15
// speedup vs baseline: 1.0323x; 1.0323x over previous
#include <cuda_runtime.h>
#include <math.h>
#include <stdint.h>

// Problem constants
#define Bc 2
#define Lc 2048
#define Dc 1024
#define Hc 16
#define Dhc 64
#define Mg (Bc*Lc)          // 4096

// Scratch
__device__ float g_q[(size_t)Bc*Hc*Lc*Dhc];
__device__ float g_k[(size_t)Bc*Hc*Lc*Dhc];
__device__ float g_v[(size_t)Bc*Hc*Lc*Dhc];   // V TRANSPOSED: [b][h][e][l]
__device__ float g_o[(size_t)Bc*Lc*Dc];
__device__ float g_xc[(size_t)Mg*Dc];        // x, tf32-rounded, [m][k]
__device__ float g_wc[(size_t)4*Dc*Dc];      // W^T {q,k,v,o}: [n][k], tf32 (Wq pre-scaled)

// ---------------------------------------------------------------------------
// Helpers
// ---------------------------------------------------------------------------
__device__ __forceinline__ uint32_t f2tf32(float f) {
    uint32_t u;
    asm("cvt.rna.tf32.f32 %0, %1;" : "=r"(u) : "f"(f));
    return u;
}

__device__ __forceinline__ float ex2(float x) {
    float r;
    asm("ex2.approx.f32 %0, %1;" : "=f"(r) : "f"(x));
    return r;
}

__device__ __forceinline__ uint32_t smem_u32(const void* p) {
    uint32_t a;
    asm("{ .reg .u64 t; cvta.to.shared.u64 t, %1; cvt.u32.u64 %0, t; }"
        : "=r"(a) : "l"(p));
    return a;
}

__device__ __forceinline__ void cpa16(uint32_t s, const void* g) {
    asm volatile("cp.async.cg.shared.global [%0], [%1], 16;" :: "r"(s), "l"(g));
}
#define CP_COMMIT() asm volatile("cp.async.commit_group;" ::: "memory")
#define CP_WAIT(n)  asm volatile("cp.async.wait_group %0;" :: "n"(n) : "memory")

__device__ __forceinline__ void mma_tf32(float* c, const uint32_t* a, const uint32_t* b) {
    asm volatile(
        "mma.sync.aligned.m16n8k8.row.col.f32.tf32.tf32.f32 "
        "{%0,%1,%2,%3}, {%4,%5,%6,%7}, {%8,%9}, {%0,%1,%2,%3};"
        : "+f"(c[0]), "+f"(c[1]), "+f"(c[2]), "+f"(c[3])
        : "r"(a[0]), "r"(a[1]), "r"(a[2]), "r"(a[3]), "r"(b[0]), "r"(b[1]));
}

// x4 ldmatrix: 4 8x(4x32b) tiles; thread gets [row=lane/4][col32=lane%4]
#define LDSM4(r, a) \
    asm volatile("ldmatrix.sync.aligned.m8n8.x4.shared.b16 {%0,%1,%2,%3}, [%4];" \
        : "=r"((r)[0]), "=r"((r)[1]), "=r"((r)[2]), "=r"((r)[3]) : "r"(a))

// ---------------------------------------------------------------------------
// Prep A: tf32-round x.
// ---------------------------------------------------------------------------
__global__ __launch_bounds__(256)
void prep_x_kernel(const float* __restrict__ x)
{
    const size_t n = (size_t)Mg * Dc;
    const size_t stride = (size_t)gridDim.x * 256 * 4;
    for (size_t i = ((size_t)blockIdx.x * 256 + threadIdx.x) * 4; i < n; i += stride) {
        float4 v = *(const float4*)(x + i);
        uint4 u;
        u.x = f2tf32(v.x); u.y = f2tf32(v.y);
        u.z = f2tf32(v.z); u.w = f2tf32(v.w);
        *(uint4*)(g_xc + i) = u;
    }
}

// ---------------------------------------------------------------------------
// Prep B: transpose weights to [n][k] + tf32 round. Wq gets (1/8)*log2(e).
// ---------------------------------------------------------------------------
__global__ __launch_bounds__(256)
void prep_w_kernel(const float* __restrict__ Wq, const float* __restrict__ Wk,
                   const float* __restrict__ Wv, const float* __restrict__ Wo)
{
    __shared__ float tile[32][33];
    const int z = blockIdx.z;
    const float* src = (z == 0) ? Wq : (z == 1) ? Wk : (z == 2) ? Wv : Wo;
    float* dst = g_wc + (size_t)z * 1048576;
    const float scale = (z == 0) ? 0.18033688011112042f : 1.0f;
    const int k0 = blockIdx.x * 32, n0 = blockIdx.y * 32;
    const int tx = threadIdx.x & 31, ty = threadIdx.x >> 5;
#pragma unroll
    for (int i = ty; i < 32; i += 8)
        tile[i][tx] = src[(size_t)(k0 + i) * 1024 + n0 + tx];
    __syncthreads();
#pragma unroll
    for (int i = ty; i < 32; i += 8)
        dst[(size_t)(n0 + i) * 1024 + k0 + tx] =
            __uint_as_float(f2tf32(tile[tx][i] * scale));
}

// ---------------------------------------------------------------------------
// cp.async 3-stage TF32 GEMM, ldmatrix fragment loads.
// Block 256x128, 8 warps (4x2), warp tile 64x64, k-chunk 32.
// mode 0: A=g_xc, B=g_wc[z]; q/k scattered [b][h][l][e], V scattered
//         TRANSPOSED [b][h][e][l]. All tf32-rounded.
// mode 1: A=g_o,  B=g_wc[3], plain fp32 row-major out
// ---------------------------------------------------------------------------
#define SA 36
#define A_ST_FL (256*SA)                 // 9216 floats
#define B_ST_FL (128*SA)                 // 4608 floats
#define STG_FL  (A_ST_FL + B_ST_FL)      // 13824
#define STG_BYTES (STG_FL*4)             // 55296
#define GEMM_SMEM (3*STG_BYTES)          // 165888 B

__global__ __launch_bounds__(256, 1)
void mma_gemm(float* __restrict__ Dst, int mode)
{
    extern __shared__ float sm[];
    const uint32_t sb = smem_u32(sm);

    const int tid = threadIdx.x;
    const int lane = tid & 31, wid = tid >> 5;
    const int g = lane >> 2, t = lane & 3;
    const int wr = wid >> 1, wc = wid & 1;

    const int n0 = blockIdx.x * 128;
    const int m0 = blockIdx.y * 256;
    const int z  = blockIdx.z;

    const float* A  = (mode == 0) ? g_xc : g_o;
    const float* Bt = g_wc + (size_t)((mode == 0) ? z : 3) * 1048576;

    const float* Agp = A  + (size_t)(m0 + (tid >> 3)) * 1024 + (tid & 7) * 4;
    const float* Bgp = Bt + (size_t)(n0 + (tid >> 3)) * 1024 + (tid & 7) * 4;
    const uint32_t aoff = (uint32_t)(tid >> 3) * (SA * 4) + (tid & 7) * 16;
    const uint32_t boff = (uint32_t)(A_ST_FL * 4) + aoff;

#define G_ISSUE(ch) do { \
    const uint32_t st_ = sb + (uint32_t)((ch) % 3) * STG_BYTES; \
    const float* ag_ = Agp + (ch) * 32; \
    const float* bg_ = Bgp + (ch) * 32; \
    _Pragma("unroll") \
    for (int i_ = 0; i_ < 8; i_++) \
        cpa16(st_ + aoff + i_ * 32 * (SA * 4), ag_ + (size_t)i_ * 32 * 1024); \
    _Pragma("unroll") \
    for (int i_ = 0; i_ < 4; i_++) \
        cpa16(st_ + boff + i_ * 32 * (SA * 4), bg_ + (size_t)i_ * 32 * 1024); \
} while (0)

    float c[4][8][4];
#pragma unroll
    for (int mi = 0; mi < 4; mi++)
#pragma unroll
        for (int ni = 0; ni < 8; ni++)
#pragma unroll
            for (int q = 0; q < 4; q++) c[mi][ni][q] = 0.f;

    G_ISSUE(0); CP_COMMIT();
    G_ISSUE(1); CP_COMMIT();

    const int mbase = 64 * wr, nbase = 64 * wc;

    const uint32_t a_lm = (uint32_t)((mbase + (lane & 15)) * SA + (lane >> 4) * 4) * 4;
    const uint32_t b_lm = (uint32_t)(A_ST_FL * 4)
        + (uint32_t)((nbase + 8 * (lane >> 4) + (lane & 7)) * SA + ((lane >> 3) & 1) * 4) * 4;

    for (int ch = 0; ch < 32; ch++) {
        CP_WAIT(1);
        __syncthreads();
        if (ch + 2 < 32) G_ISSUE(ch + 2);
        CP_COMMIT();

        const uint32_t st = sb + (uint32_t)(ch % 3) * STG_BYTES;
        const uint32_t aB = st + a_lm;
        const uint32_t bB = st + b_lm;
#pragma unroll
        for (int ks = 0; ks < 4; ks++) {
            const int kk = ks * 8;
            uint32_t af[4][4], bf[4][4];
#pragma unroll
            for (int mi = 0; mi < 4; mi++)
                LDSM4(af[mi], aB + (uint32_t)(mi * 16 * SA + kk) * 4);
#pragma unroll
            for (int p = 0; p < 4; p++)
                LDSM4(bf[p], bB + (uint32_t)(p * 16 * SA + kk) * 4);
#pragma unroll
            for (int mi = 0; mi < 4; mi++)
#pragma unroll
                for (int ni = 0; ni < 8; ni++)
                    mma_tf32(c[mi][ni], af[mi], &bf[ni >> 1][2 * (ni & 1)]);
        }
    }

    // Epilogue
    float* gz = (mode == 0) ? ((z == 0) ? g_q : (z == 1) ? g_k : g_v) : Dst;
#pragma unroll
    for (int mi = 0; mi < 4; mi++) {
#pragma unroll
        for (int half = 0; half < 2; half++) {
            const int mglob = m0 + mbase + 16*mi + g + 8*half;
#pragma unroll
            for (int ni = 0; ni < 8; ni++) {
                const int nglob = n0 + nbase + 8*ni + 2*t;
                float2 v;
                v.x = c[mi][ni][2*half + 0];
                v.y = c[mi][ni][2*half + 1];
                if (mode == 0) {
                    v.x = __uint_as_float(f2tf32(v.x));
                    v.y = __uint_as_float(f2tf32(v.y));
                    const int b = mglob >> 11, l = mglob & 2047;
                    const int h = nglob >> 6, e = nglob & 63;
                    if (z == 2) {
                        // V transposed: [b][h][e][l]
                        float* vtb = gz + (((size_t)(b*Hc + h) << 6) << 11);
                        vtb[((size_t)e << 11) + l]       = v.x;
                        vtb[((size_t)(e + 1) << 11) + l] = v.y;
                    } else {
                        *(float2*)&gz[(((size_t)(b*Hc + h) * Lc + l) << 6) + e] = v;
                    }
                } else {
                    *(float2*)&gz[(size_t)mglob * 1024 + nglob] = v;
                }
            }
        }
    }
}

// ---------------------------------------------------------------------------
// TF32 tensor-core causal flash attention. ldmatrix for ALL fragments:
// Q/P ([m][k] rows), K ([n][k] rows), V^T ([e][l] rows — V pre-transposed
// in gmem by the QKV epilogue). K/V split commit groups.
// Block: 128 q-rows (8 warps x 16), K-tile 64.
// ---------------------------------------------------------------------------
#define SQf 68
#define SKf 68
#define SVf 68
#define SPf 68
#define QS_OFF 0
#define KS_OFF (128*SQf)                 // 8704
#define VS_OFF (KS_OFF + 64*SKf)         // 13056
#define PS_OFF (VS_OFF + 64*SVf)         // 17408
#define FL_FLOATS (PS_OFF + 128*SPf)     // 26112
#define FL_SMEM (FL_FLOATS * 4)          // 104448 B

__global__ __launch_bounds__(256, 2)
void flash_kernel()
{
    extern __shared__ float sm[];
    const uint32_t sb = smem_u32(sm);
    float* Ps = sm + PS_OFF;

    const int qt = gridDim.x - 1 - blockIdx.x;   // heavy tiles first
    const int bh = blockIdx.y;
    const int tid = threadIdx.x;
    const int lane = tid & 31, wid = tid >> 5;
    const int g = lane >> 2, t = lane & 3;
    const int wq0 = wid * 16;

    const float* qb = g_q + (size_t)bh * Lc * Dhc;
    const float* kb = g_k + (size_t)bh * Lc * Dhc;
    const float* vb = g_v + (size_t)bh * Lc * Dhc;   // [e][l], stride Lc

    // ldmatrix bases (byte offsets)
    const uint32_t q_lm = sb + (uint32_t)((wq0 + (lane & 15)) * SQf + (lane >> 4) * 4) * 4;
    const uint32_t k_lm = sb + (uint32_t)(KS_OFF
        + (8 * (lane >> 4) + (lane & 7)) * SKf + ((lane >> 3) & 1) * 4) * 4;
    const uint32_t v_lm = sb + (uint32_t)(VS_OFF
        + (8 * (lane >> 4) + (lane & 7)) * SVf + ((lane >> 3) & 1) * 4) * 4;
    const uint32_t p_lm = sb + (uint32_t)(PS_OFF
        + (wq0 + (lane & 15)) * SPf + (lane >> 4) * 4) * 4;

    // Q tile (128 x 64) via cp.async (already scaled + tf32)
#pragma unroll
    for (int it = 0; it < 8; it++) {
        const int idx = it * 256 + tid;
        const int r = idx >> 4, c4 = (idx & 15) * 4;
        cpa16(sb + (uint32_t)(r * SQf + c4) * 4,
              qb + (size_t)(qt * 128 + r) * 64 + c4);
    }
    CP_COMMIT();

    float m2[2] = {-1e30f, -1e30f};
    float lsum[2] = {0.f, 0.f};
    float o[8][4];
#pragma unroll
    for (int ni = 0; ni < 8; ni++)
#pragma unroll
        for (int q = 0; q < 4; q++) o[ni][q] = 0.f;

    const int kend = 2 * qt + 1;
    for (int kt = 0; kt <= kend; kt++) {
        __syncthreads();   // prior iter's K/V reads complete
        // K group: 64 rows (l) x 64 (e)
#pragma unroll
        for (int it = 0; it < 4; it++) {
            const int idx = it * 256 + tid;
            const int r = idx >> 4, c4 = (idx & 15) * 4;
            cpa16(sb + (uint32_t)(KS_OFF + r * SKf + c4) * 4,
                  kb + (size_t)(kt * 64 + r) * 64 + c4);
        }
        CP_COMMIT();
        // V^T group: 64 rows (e) x 64 (l window) — overlaps QK^T compute
#pragma unroll
        for (int it = 0; it < 4; it++) {
            const int idx = it * 256 + tid;
            const int r = idx >> 4, c4 = (idx & 15) * 4;
            cpa16(sb + (uint32_t)(VS_OFF + r * SVf + c4) * 4,
                  vb + ((size_t)r << 11) + kt * 64 + c4);
        }
        CP_COMMIT();

        CP_WAIT(1);        // K ready (V may still be in flight)
        __syncthreads();

        // S = Q K^T  (warp: 16 x 64, k=64)
        float s[8][4];
#pragma unroll
        for (int ni = 0; ni < 8; ni++)
#pragma unroll
            for (int q = 0; q < 4; q++) s[ni][q] = 0.f;

#pragma unroll
        for (int ks = 0; ks < 8; ks++) {
            const int kk = ks * 8;
            uint32_t a[4], bf[4][4];
            LDSM4(a, q_lm + kk * 4);
#pragma unroll
            for (int p = 0; p < 4; p++)
                LDSM4(bf[p], k_lm + (uint32_t)(p * 16 * SKf + kk) * 4);
#pragma unroll
            for (int ni = 0; ni < 8; ni++)
                mma_tf32(s[ni], a, &bf[ni >> 1][2 * (ni & 1)]);
        }

        // Causal mask (near-diagonal tiles only)
        if (kt >= 2 * qt) {
            const int q0r = qt * 128 + wq0 + g;
#pragma unroll
            for (int ni = 0; ni < 8; ni++) {
                const int key0 = kt * 64 + ni * 8 + 2 * t;
                if (key0     > q0r)     s[ni][0] = -1e30f;
                if (key0 + 1 > q0r)     s[ni][1] = -1e30f;
                if (key0     > q0r + 8) s[ni][2] = -1e30f;
                if (key0 + 1 > q0r + 8) s[ni][3] = -1e30f;
            }
        }

        // Online softmax (rows g, g+8). Ps rows warp-private -> syncwarp.
        __syncwarp();
#pragma unroll
        for (int rr = 0; rr < 2; rr++) {
            float mx = -1e30f;
#pragma unroll
            for (int ni = 0; ni < 8; ni++)
                mx = fmaxf(mx, fmaxf(s[ni][2*rr], s[ni][2*rr + 1]));
            mx = fmaxf(mx, __shfl_xor_sync(0xffffffffu, mx, 1));
            mx = fmaxf(mx, __shfl_xor_sync(0xffffffffu, mx, 2));
            const float mnew = fmaxf(m2[rr], mx);
            const float corr = ex2(m2[rr] - mnew);
            float rs = 0.f;
#pragma unroll
            for (int ni = 0; ni < 8; ni++) {
                const float p0 = ex2(s[ni][2*rr]     - mnew);
                const float p1 = ex2(s[ni][2*rr + 1] - mnew);
                rs += p0 + p1;
                uint2 pw;
                pw.x = f2tf32(p0); pw.y = f2tf32(p1);
                *(uint2*)(Ps + (wq0 + g + 8*rr) * SPf + ni * 8 + 2 * t) = pw;
            }
            rs += __shfl_xor_sync(0xffffffffu, rs, 1);
            rs += __shfl_xor_sync(0xffffffffu, rs, 2);
            lsum[rr] = lsum[rr] * corr + rs;
            m2[rr] = mnew;
#pragma unroll
            for (int ni = 0; ni < 8; ni++) {
                o[ni][2*rr]     *= corr;
                o[ni][2*rr + 1] *= corr;
            }
        }
        __syncwarp();

        CP_WAIT(0);        // V ready
        __syncthreads();

        // O += P V  (P and V^T both via ldmatrix)
#pragma unroll
        for (int ks = 0; ks < 8; ks++) {
            const int kk = ks * 8;
            uint32_t a[4], vf[4][4];
            LDSM4(a, p_lm + kk * 4);
#pragma unroll
            for (int p = 0; p < 4; p++)
                LDSM4(vf[p], v_lm + (uint32_t)(p * 16 * SVf + kk) * 4);
#pragma unroll
            for (int ni = 0; ni < 8; ni++)
                mma_tf32(o[ni], a, &vf[ni >> 1][2 * (ni & 1)]);
        }
    }

    // Epilogue: normalize, tf32-round (feeds out-proj mma), write g_o
    const float inv0 = 1.0f / lsum[0];
    const float inv1 = 1.0f / lsum[1];
    const int b = bh >> 4, h = bh & 15;
    const int q0 = qt * 128 + wq0 + g;
    const size_t base0 = ((size_t)(b * Lc + q0)) * Dc + h * Dhc;
    const size_t base1 = base0 + (size_t)8 * Dc;
#pragma unroll
    for (int ni = 0; ni < 8; ni++) {
        float2 v0, v1;
        v0.x = __uint_as_float(f2tf32(o[ni][0] * inv0));
        v0.y = __uint_as_float(f2tf32(o[ni][1] * inv0));
        v1.x = __uint_as_float(f2tf32(o[ni][2] * inv1));
        v1.y = __uint_as_float(f2tf32(o[ni][3] * inv1));
        *(float2*)&g_o[base0 + ni * 8 + 2 * t] = v0;
        *(float2*)&g_o[base1 + ni * 8 + 2 * t] = v1;
    }
}

// ---------------------------------------------------------------------------
extern "C" void kernel_launch(void* const* d_in, const int* in_sizes, int n_in,
                              void* d_out, int out_size)
{
    const float* x    = (const float*)d_in[0];
    const float* Wq   = (const float*)d_in[1];
    const float* Wk   = (const float*)d_in[2];
    const float* Wv   = (const float*)d_in[3];
    const float* Wout = (const float*)d_in[4];
    float* out = (float*)d_out;

    cudaFuncSetAttribute(mma_gemm,
                         cudaFuncAttributeMaxDynamicSharedMemorySize, GEMM_SMEM);
    cudaFuncSetAttribute(flash_kernel,
                         cudaFuncAttributeMaxDynamicSharedMemorySize, FL_SMEM);

    // 0) one-time prep: round x; transpose+round weights (Wq pre-scaled)
    prep_x_kernel<<<512, 256>>>(x);
    prep_w_kernel<<<dim3(32, 32, 4), 256>>>(Wq, Wk, Wv, Wout);

    // 1) QKV: q/k -> [b][h][l][e]; V -> [b][h][e][l] (transposed)
    mma_gemm<<<dim3(8, 16, 3), 256, GEMM_SMEM>>>(nullptr, 0);

    // 2) Flash attention (tf32, all-ldmatrix)
    flash_kernel<<<dim3(Lc / 128, Bc * Hc), 256, FL_SMEM>>>();

    // 3) Output projection
    mma_gemm<<<dim3(8, 16, 1), 256, GEMM_SMEM>>>(out, 1);
}